// round 13
// baseline (speedup 1.0000x reference)
#include <cuda_runtime.h>
#include <cuda_bf16.h>

#define NMAX   50000
#define EMAX   800000
#define FEAT   128
#define HID    64
#define NCLS   16

// ---- device scratch (no allocations allowed) ----
__device__ int   g_cnt [NMAX];     // in-degree (excl. self-loop)
__device__ int   g_off [NMAX];     // CSR offsets (destructively consumed by place)
__device__ float g_dinv[NMAX];
__device__ int2  g_epack[EMAX];    // CSR: (src, norm_bits) sorted by dst
__device__ float g_bufA[(size_t)NMAX * HID];
__device__ float g_bufB[(size_t)NMAX * HID];
__device__ int   g_is64;

__device__ __forceinline__ float* bufptr(int sel) { return sel ? g_bufB : g_bufA; }

__device__ __forceinline__ int edge_at(const void* __restrict__ idx, long long i) {
    if (g_is64) return (int)((const long long*)idx)[i];
    return ((const int*)idx)[i];
}

// ---- prep: zero degree counts; block 0 detects index dtype in parallel ----
__global__ void k_prep(const void* __restrict__ idx, int n) {
    int i = blockIdx.x * 256 + threadIdx.x;
    if (i < n) g_cnt[i] = 0;
    if (blockIdx.x == 0) {
        __shared__ int sok[8];
        int ok = 1;
        #pragma unroll
        for (int j = 0; j < 4; j++) {
            long long v = ((const long long*)idx)[threadIdx.x * 4 + j];
            if (v < 0 || v >= n) ok = 0;
        }
        unsigned m = __ballot_sync(0xffffffffu, ok);
        if ((threadIdx.x & 31) == 0) sok[threadIdx.x >> 5] = (m == 0xffffffffu);
        __syncthreads();
        if (threadIdx.x == 0) {
            int all = 1;
            #pragma unroll
            for (int w = 0; w < 8; w++) all &= sok[w];
            g_is64 = all;
        }
    }
}

// ---- count in-degrees: 1 edge per thread ----
__global__ void k_deg(const void* __restrict__ idx, long long E) {
    long long e = (long long)blockIdx.x * 256 + threadIdx.x;
    if (e >= E) return;
    atomicAdd(&g_cnt[edge_at(idx, E + e)], 1);
}

// ---- single-block exclusive scan of g_cnt -> g_off (4/thread) ; also dinv ----
__global__ void k_scan(int n) {
    __shared__ int wsum[32];
    __shared__ int s_carry;
    int t = threadIdx.x;                 // 1024 threads
    int lane = t & 31, wid = t >> 5;
    if (t == 0) s_carry = 0;
    __syncthreads();
    int nIter = (n + 4095) / 4096;
    for (int it = 0; it < nIter; it++) {
        int base = it * 4096 + t * 4;
        int4 c = make_int4(0, 0, 0, 0);
        if (base + 3 < n) c = *(const int4*)(g_cnt + base);
        else {
            if (base     < n) c.x = g_cnt[base];
            if (base + 1 < n) c.y = g_cnt[base + 1];
            if (base + 2 < n) c.z = g_cnt[base + 2];
        }
        int v = c.x + c.y + c.z + c.w;
        int x = v;
        #pragma unroll
        for (int o = 1; o < 32; o <<= 1) {
            int y = __shfl_up_sync(0xffffffffu, x, o);
            if (lane >= o) x += y;
        }
        if (lane == 31) wsum[wid] = x;
        __syncthreads();
        if (t < 32) {
            int w = wsum[t], xs = w;
            #pragma unroll
            for (int o = 1; o < 32; o <<= 1) {
                int y = __shfl_up_sync(0xffffffffu, xs, o);
                if (t >= o) xs += y;
            }
            wsum[t] = xs - w;            // exclusive warp prefix
        }
        __syncthreads();
        int excl = x - v + wsum[wid] + s_carry;
        if (base + 3 < n) {
            *(int4*)(g_off + base) = make_int4(excl, excl + c.x,
                                               excl + c.x + c.y,
                                               excl + c.x + c.y + c.z);
            *(float4*)(g_dinv + base) = make_float4(
                rsqrtf((float)c.x + 1.0f), rsqrtf((float)c.y + 1.0f),
                rsqrtf((float)c.z + 1.0f), rsqrtf((float)c.w + 1.0f));
        } else {
            int run = excl;
            if (base < n)     { g_off[base]   = run; g_dinv[base]   = rsqrtf((float)c.x + 1.0f); run += c.x; }
            if (base + 1 < n) { g_off[base+1] = run; g_dinv[base+1] = rsqrtf((float)c.y + 1.0f); run += c.y; }
            if (base + 2 < n) { g_off[base+2] = run; g_dinv[base+2] = rsqrtf((float)c.z + 1.0f); }
        }
        __syncthreads();
        if (t == 1023) s_carry = excl + v;
        __syncthreads();
    }
}

// ---- FUSED: gemm1 (blocks [0,nGemm)) + CSR placement (remaining blocks). ----
template<int K>
__global__ void __launch_bounds__(256, 4) k_gemm_place(
        const float* __restrict__ Aext, int in_sel, int raw_sel,
        const float* __restrict__ W, int n,
        const void* __restrict__ idx, long long E, int nGemm) {
    constexpr int KC = 32;
    __shared__ float sWc[KC * HID];               // 8KB chunk of W
    __shared__ unsigned long long sx2[64 * KC];   // 16KB (a,a) duplicated
    int t = threadIdx.x;

    if (blockIdx.x >= nGemm) {
        // ---- placement half: 1 edge per thread ----
        long long e = (long long)(blockIdx.x - nGemm) * 256 + t;
        if (e < E) {
            int s = edge_at(idx, e);
            int d = edge_at(idx, E + e);
            int pos = atomicAdd(&g_off[d], 1);
            float norm = g_dinv[s] * g_dinv[d];
            g_epack[pos] = make_int2(s, __float_as_int(norm));
        }
        return;
    }

    // ---- gemm half ----
    const float* A = (in_sel < 0) ? Aext : bufptr(in_sel);
    float* Oraw = bufptr(raw_sel);
    int tx = t & 15, ty = t >> 4;
    int node0 = blockIdx.x * 64;

    unsigned long long acc[4][2];
    #pragma unroll
    for (int i = 0; i < 4; i++) { acc[i][0] = 0ull; acc[i][1] = 0ull; }

    const float4* Av = (const float4*)A;
    #pragma unroll
    for (int kc = 0; kc < K / KC; kc++) {
        __syncthreads();
        #pragma unroll
        for (int j = 0; j < 2; j++)
            ((float4*)sWc)[t + j * 256] =
                ((const float4*)(W + (size_t)kc * KC * HID))[t + j * 256];
        #pragma unroll
        for (int j = 0; j < 2; j++) {
            int i = t + j * 256;
            int r = i >> 3, kv = i & 7;
            int node = node0 + r;
            float4 v = make_float4(0.f, 0.f, 0.f, 0.f);
            if (node < n) v = Av[(size_t)node * (K / 4) + kc * (KC / 4) + kv];
            float4* dst = (float4*)(sx2 + (size_t)r * KC + kv * 4);
            dst[0] = make_float4(v.x, v.x, v.y, v.y);
            dst[1] = make_float4(v.z, v.z, v.w, v.w);
        }
        __syncthreads();
        #pragma unroll
        for (int k = 0; k < KC; k++) {
            ulonglong2 wv = ((const ulonglong2*)sWc)[(size_t)k * 16 + tx];
            #pragma unroll
            for (int i = 0; i < 4; i++) {
                unsigned long long aa = sx2[(size_t)(ty * 4 + i) * KC + k];
                asm("fma.rn.f32x2 %0, %1, %2, %0;" : "+l"(acc[i][0]) : "l"(aa), "l"(wv.x));
                asm("fma.rn.f32x2 %0, %1, %2, %0;" : "+l"(acc[i][1]) : "l"(aa), "l"(wv.y));
            }
        }
    }

    #pragma unroll
    for (int i = 0; i < 4; i++) {
        int node = node0 + ty * 4 + i;
        if (node >= n) break;
        unsigned lo0, hi0, lo1, hi1;
        asm("mov.b64 {%0, %1}, %2;" : "=r"(lo0), "=r"(hi0) : "l"(acc[i][0]));
        asm("mov.b64 {%0, %1}, %2;" : "=r"(lo1), "=r"(hi1) : "l"(acc[i][1]));
        ((float4*)Oraw)[(size_t)node * (HID / 4) + tx] =
            make_float4(__uint_as_float(lo0), __uint_as_float(hi0),
                        __uint_as_float(lo1), __uint_as_float(hi1));
    }
}

// ---- plain register-blocked GEMM (layer 2) ----
template<int K>
__global__ void __launch_bounds__(256, 4) k_gemm(
        const float* __restrict__ Aext, int in_sel, int raw_sel,
        const float* __restrict__ W, int n) {
    constexpr int KC = 32;
    __shared__ float sWc[KC * HID];
    __shared__ unsigned long long sx2[64 * KC];
    const float* A = (in_sel < 0) ? Aext : bufptr(in_sel);
    float* Oraw = bufptr(raw_sel);
    int t  = threadIdx.x;
    int tx = t & 15, ty = t >> 4;
    int node0 = blockIdx.x * 64;

    unsigned long long acc[4][2];
    #pragma unroll
    for (int i = 0; i < 4; i++) { acc[i][0] = 0ull; acc[i][1] = 0ull; }

    const float4* Av = (const float4*)A;
    #pragma unroll
    for (int kc = 0; kc < K / KC; kc++) {
        __syncthreads();
        #pragma unroll
        for (int j = 0; j < 2; j++)
            ((float4*)sWc)[t + j * 256] =
                ((const float4*)(W + (size_t)kc * KC * HID))[t + j * 256];
        #pragma unroll
        for (int j = 0; j < 2; j++) {
            int i = t + j * 256;
            int r = i >> 3, kv = i & 7;
            int node = node0 + r;
            float4 v = make_float4(0.f, 0.f, 0.f, 0.f);
            if (node < n) v = Av[(size_t)node * (K / 4) + kc * (KC / 4) + kv];
            float4* dst = (float4*)(sx2 + (size_t)r * KC + kv * 4);
            dst[0] = make_float4(v.x, v.x, v.y, v.y);
            dst[1] = make_float4(v.z, v.z, v.w, v.w);
        }
        __syncthreads();
        #pragma unroll
        for (int k = 0; k < KC; k++) {
            ulonglong2 wv = ((const ulonglong2*)sWc)[(size_t)k * 16 + tx];
            #pragma unroll
            for (int i = 0; i < 4; i++) {
                unsigned long long aa = sx2[(size_t)(ty * 4 + i) * KC + k];
                asm("fma.rn.f32x2 %0, %1, %2, %0;" : "+l"(acc[i][0]) : "l"(aa), "l"(wv.x));
                asm("fma.rn.f32x2 %0, %1, %2, %0;" : "+l"(acc[i][1]) : "l"(aa), "l"(wv.y));
            }
        }
    }

    #pragma unroll
    for (int i = 0; i < 4; i++) {
        int node = node0 + ty * 4 + i;
        if (node >= n) break;
        unsigned lo0, hi0, lo1, hi1;
        asm("mov.b64 {%0, %1}, %2;" : "=r"(lo0), "=r"(hi0) : "l"(acc[i][0]));
        asm("mov.b64 {%0, %1}, %2;" : "=r"(lo1), "=r"(hi1) : "l"(acc[i][1]));
        ((float4*)Oraw)[(size_t)node * (HID / 4) + tx] =
            make_float4(__uint_as_float(lo0), __uint_as_float(hi0),
                        __uint_as_float(lo1), __uint_as_float(hi1));
    }
}

// ---- shared CSR accumulate: coalesced edge staging + half-warp shfl broadcast.
//      Half-warp (16 lanes, same node) loads 16 edge-packs coalesced, then
//      broadcasts each (src, norm) via shfl; gathers stay 4-wide for MLP. ----
__device__ __forceinline__ float4 csr_accum(const float* __restrict__ raw,
                                            int node, int i, unsigned hmask) {
    int end = g_off[node], cnt = g_cnt[node], e0 = end - cnt;
    float dv = g_dinv[node];
    float s2 = dv * dv;
    float4 acc = ((const float4*)(raw + (size_t)node * HID))[i];
    acc.x *= s2; acc.y *= s2; acc.z *= s2; acc.w *= s2;

    for (int base = e0; base < end; base += 16) {
        int nloc = end - base; if (nloc > 16) nloc = 16;
        int ms = 0, mn = 0;
        if (i < nloc) { int2 p = g_epack[base + i]; ms = p.x; mn = p.y; }
        int j = 0;
        for (; j + 3 < nloc; j += 4) {
            int s0 = __shfl_sync(hmask, ms, j,     16);
            int b0 = __shfl_sync(hmask, mn, j,     16);
            int s1 = __shfl_sync(hmask, ms, j + 1, 16);
            int b1 = __shfl_sync(hmask, mn, j + 1, 16);
            int s2i= __shfl_sync(hmask, ms, j + 2, 16);
            int b2 = __shfl_sync(hmask, mn, j + 2, 16);
            int s3 = __shfl_sync(hmask, ms, j + 3, 16);
            int b3 = __shfl_sync(hmask, mn, j + 3, 16);
            float4 v0 = __ldg((const float4*)(raw + (size_t)s0  * HID) + i);
            float4 v1 = __ldg((const float4*)(raw + (size_t)s1  * HID) + i);
            float4 v2 = __ldg((const float4*)(raw + (size_t)s2i * HID) + i);
            float4 v3 = __ldg((const float4*)(raw + (size_t)s3  * HID) + i);
            float n0 = __int_as_float(b0), n1 = __int_as_float(b1);
            float n2 = __int_as_float(b2), n3 = __int_as_float(b3);
            acc.x += v0.x * n0; acc.y += v0.y * n0; acc.z += v0.z * n0; acc.w += v0.w * n0;
            acc.x += v1.x * n1; acc.y += v1.y * n1; acc.z += v1.z * n1; acc.w += v1.w * n1;
            acc.x += v2.x * n2; acc.y += v2.y * n2; acc.z += v2.z * n2; acc.w += v2.w * n2;
            acc.x += v3.x * n3; acc.y += v3.y * n3; acc.z += v3.z * n3; acc.w += v3.w * n3;
        }
        for (; j < nloc; j++) {
            int s0 = __shfl_sync(hmask, ms, j, 16);
            int b0 = __shfl_sync(hmask, mn, j, 16);
            float4 v0 = __ldg((const float4*)(raw + (size_t)s0 * HID) + i);
            float n0 = __int_as_float(b0);
            acc.x += v0.x * n0; acc.y += v0.y * n0; acc.z += v0.z * n0; acc.w += v0.w * n0;
        }
    }
    return acc;
}

// ---- layer-1 aggregation: half-warp per node; fused bias + relu ----
__global__ void k_agg(int in_sel, int out_sel, const float* __restrict__ b, int n) {
    int t = threadIdx.x;
    int node = blockIdx.x * 16 + (t >> 4);
    if (node >= n) return;
    int i = t & 15;
    unsigned hmask = 0xFFFFu << (t & 16);    // lanes of this half-warp
    const float* raw = bufptr(in_sel);
    float* outb = bufptr(out_sel);
    float4 acc = csr_accum(raw, node, i, hmask);
    float4 bb = ((const float4*)b)[i];
    acc.x = fmaxf(acc.x + bb.x, 0.f); acc.y = fmaxf(acc.y + bb.y, 0.f);
    acc.z = fmaxf(acc.z + bb.z, 0.f); acc.w = fmaxf(acc.w + bb.w, 0.f);
    ((float4*)(outb + (size_t)node * HID))[i] = acc;
}

// ---- layer-2 aggregation fused with output head ----
__global__ void k_agg_out(int in_sel, const float* __restrict__ b2,
                          const float* __restrict__ Wout,
                          const float* __restrict__ bout,
                          float* __restrict__ out, int n) {
    constexpr int RP = HID + 4;                 // padded row stride (bank-safe)
    __shared__ float sW[HID * NCLS];            // 4 KB
    __shared__ float sh[16 * RP];
    int t = threadIdx.x;                        // 256 threads
    ((float4*)sW)[t] = ((const float4*)Wout)[t];    // HID*NCLS/4 == 256
    int node = blockIdx.x * 16 + (t >> 4);
    int i = t & 15;
    unsigned hmask = 0xFFFFu << (t & 16);
    float4 acc = make_float4(0.f, 0.f, 0.f, 0.f);
    if (node < n) {
        const float* raw = bufptr(in_sel);
        acc = csr_accum(raw, node, i, hmask);
        float4 bb = ((const float4*)b2)[i];
        acc.x = fmaxf(acc.x + bb.x, 0.f); acc.y = fmaxf(acc.y + bb.y, 0.f);
        acc.z = fmaxf(acc.z + bb.z, 0.f); acc.w = fmaxf(acc.w + bb.w, 0.f);
    }
    ((float4*)(sh + (t >> 4) * RP))[i] = acc;
    __syncthreads();
    if (node >= n) return;
    int c = i;
    const float* hr = sh + (t >> 4) * RP;
    float lg = bout[c];
    #pragma unroll
    for (int k = 0; k < HID; k++)
        lg += hr[k] * sW[k * NCLS + c];
    float m = lg;
    #pragma unroll
    for (int o = 8; o; o >>= 1) m = fmaxf(m, __shfl_xor_sync(0xffffffffu, m, o, 16));
    float e = __expf(lg - m);
    float s = e;
    #pragma unroll
    for (int o = 8; o; o >>= 1) s += __shfl_xor_sync(0xffffffffu, s, o, 16);
    out[(size_t)node * NCLS + c] = e / s;
}

extern "C" void kernel_launch(void* const* d_in, const int* in_sizes, int n_in,
                              void* d_out, int out_size) {
    const float* x    = (const float*)d_in[0];
    const void*  ei   = d_in[1];
    const float* W1   = (const float*)d_in[2];
    const float* b1   = (const float*)d_in[3];
    const float* W2   = (const float*)d_in[4];
    const float* b2   = (const float*)d_in[5];
    const float* Wout = (const float*)d_in[6];
    const float* bout = (const float*)d_in[7];
    float* out = (float*)d_out;

    int       n = in_sizes[0] / FEAT;
    long long E = (long long)in_sizes[1] / 2;

    int nb_n  = (n + 255) / 256;
    int nb_e  = (int)((E + 255) / 256);       // 1 edge per thread
    int nb_gm = (n + 63) / 64;
    int nb_ag = (n + 15) / 16;

    // CSR build (place overlapped with gemm1 below)
    k_prep<<<nb_n, 256>>>(ei, n);
    k_deg<<<nb_e, 256>>>(ei, E);
    k_scan<<<1, 1024>>>(n);

    // fused: gemm1 (x@W1 -> bufA) + CSR placement, one launch
    k_gemm_place<FEAT><<<nb_gm + nb_e, 256>>>(x, -1, 0, W1, n, ei, E, nb_gm);

    // layer 1 aggregation: agg(+b1,relu) -> bufB
    k_agg<<<nb_ag, 256>>>(0, 1, b1, n);

    // layer 2: raw = bufB@W2 -> bufA
    k_gemm<HID><<<nb_gm, 256>>>(nullptr, 1, 0, W2, n);

    // agg2(+b2,relu) + head -> out
    k_agg_out<<<nb_ag, 256>>>(0, b2, Wout, bout, out, n);
}

// round 14
// speedup vs baseline: 1.0544x; 1.0544x over previous
#include <cuda_runtime.h>
#include <cuda_bf16.h>

#define NMAX   50000
#define EMAX   800000
#define FEAT   128
#define HID    64
#define NCLS   16

// ---- device scratch (no allocations allowed) ----
__device__ int   g_cnt [NMAX];     // in-degree (excl. self-loop)
__device__ int   g_off [NMAX];     // CSR offsets (destructively consumed by place)
__device__ float g_dinv[NMAX];
__device__ int2  g_epack[EMAX];    // CSR: (src, norm_bits) sorted by dst
__device__ float g_bufA[(size_t)NMAX * HID];
__device__ float g_bufB[(size_t)NMAX * HID];
__device__ int   g_is64;

__device__ __forceinline__ float* bufptr(int sel) { return sel ? g_bufB : g_bufA; }

__device__ __forceinline__ int edge_at(const void* __restrict__ idx, long long i) {
    if (g_is64) return (int)((const long long*)idx)[i];
    return ((const int*)idx)[i];
}

// ---- prep: zero degree counts; block 0 detects index dtype in parallel ----
__global__ void k_prep(const void* __restrict__ idx, int n) {
    int i = blockIdx.x * 256 + threadIdx.x;
    if (i < n) g_cnt[i] = 0;
    if (blockIdx.x == 0) {
        __shared__ int sok[8];
        int ok = 1;
        #pragma unroll
        for (int j = 0; j < 4; j++) {
            long long v = ((const long long*)idx)[threadIdx.x * 4 + j];
            if (v < 0 || v >= n) ok = 0;
        }
        unsigned m = __ballot_sync(0xffffffffu, ok);
        if ((threadIdx.x & 31) == 0) sok[threadIdx.x >> 5] = (m == 0xffffffffu);
        __syncthreads();
        if (threadIdx.x == 0) {
            int all = 1;
            #pragma unroll
            for (int w = 0; w < 8; w++) all &= sok[w];
            g_is64 = all;
        }
    }
}

// ---- count in-degrees: 1 edge per thread ----
__global__ void k_deg(const void* __restrict__ idx, long long E) {
    long long e = (long long)blockIdx.x * 256 + threadIdx.x;
    if (e >= E) return;
    atomicAdd(&g_cnt[edge_at(idx, E + e)], 1);
}

// ---- single-block exclusive scan of g_cnt -> g_off (4/thread) ; also dinv ----
__global__ void k_scan(int n) {
    __shared__ int wsum[32];
    __shared__ int s_carry;
    int t = threadIdx.x;                 // 1024 threads
    int lane = t & 31, wid = t >> 5;
    if (t == 0) s_carry = 0;
    __syncthreads();
    int nIter = (n + 4095) / 4096;
    for (int it = 0; it < nIter; it++) {
        int base = it * 4096 + t * 4;
        int4 c = make_int4(0, 0, 0, 0);
        if (base + 3 < n) c = *(const int4*)(g_cnt + base);
        else {
            if (base     < n) c.x = g_cnt[base];
            if (base + 1 < n) c.y = g_cnt[base + 1];
            if (base + 2 < n) c.z = g_cnt[base + 2];
        }
        int v = c.x + c.y + c.z + c.w;
        int x = v;
        #pragma unroll
        for (int o = 1; o < 32; o <<= 1) {
            int y = __shfl_up_sync(0xffffffffu, x, o);
            if (lane >= o) x += y;
        }
        if (lane == 31) wsum[wid] = x;
        __syncthreads();
        if (t < 32) {
            int w = wsum[t], xs = w;
            #pragma unroll
            for (int o = 1; o < 32; o <<= 1) {
                int y = __shfl_up_sync(0xffffffffu, xs, o);
                if (t >= o) xs += y;
            }
            wsum[t] = xs - w;            // exclusive warp prefix
        }
        __syncthreads();
        int excl = x - v + wsum[wid] + s_carry;
        if (base + 3 < n) {
            *(int4*)(g_off + base) = make_int4(excl, excl + c.x,
                                               excl + c.x + c.y,
                                               excl + c.x + c.y + c.z);
            *(float4*)(g_dinv + base) = make_float4(
                rsqrtf((float)c.x + 1.0f), rsqrtf((float)c.y + 1.0f),
                rsqrtf((float)c.z + 1.0f), rsqrtf((float)c.w + 1.0f));
        } else {
            int run = excl;
            if (base < n)     { g_off[base]   = run; g_dinv[base]   = rsqrtf((float)c.x + 1.0f); run += c.x; }
            if (base + 1 < n) { g_off[base+1] = run; g_dinv[base+1] = rsqrtf((float)c.y + 1.0f); run += c.y; }
            if (base + 2 < n) { g_off[base+2] = run; g_dinv[base+2] = rsqrtf((float)c.z + 1.0f); }
        }
        __syncthreads();
        if (t == 1023) s_carry = excl + v;
        __syncthreads();
    }
}

// ---- FUSED: gemm1 + CSR placement, INTERLEAVED block roles so both kinds
//      coexist in every wave (gemm = fma-bound, place = latency-bound). ----
template<int K>
__global__ void __launch_bounds__(256, 4) k_gemm_place(
        const float* __restrict__ Aext, int in_sel, int raw_sel,
        const float* __restrict__ W, int n,
        const void* __restrict__ idx, long long E, int nGemm, int R) {
    constexpr int KC = 32;
    __shared__ float sWc[KC * HID];               // 8KB chunk of W
    __shared__ unsigned long long sx2[64 * KC];   // 16KB (a,a) duplicated
    int t = threadIdx.x;
    int bid = blockIdx.x;

    bool isGemm = (bid % R == 0) && (bid / R < nGemm);
    if (!isGemm) {
        // ---- placement half: 1 edge per thread ----
        int gBefore = bid / R + 1; if (gBefore > nGemm) gBefore = nGemm;
        long long e = (long long)(bid - gBefore) * 256 + t;
        if (e < E) {
            int s = edge_at(idx, e);
            int d = edge_at(idx, E + e);
            int pos = atomicAdd(&g_off[d], 1);
            float norm = g_dinv[s] * g_dinv[d];
            g_epack[pos] = make_int2(s, __float_as_int(norm));
        }
        return;
    }

    // ---- gemm half ----
    const float* A = (in_sel < 0) ? Aext : bufptr(in_sel);
    float* Oraw = bufptr(raw_sel);
    int tx = t & 15, ty = t >> 4;
    int node0 = (bid / R) * 64;

    unsigned long long acc[4][2];
    #pragma unroll
    for (int i = 0; i < 4; i++) { acc[i][0] = 0ull; acc[i][1] = 0ull; }

    const float4* Av = (const float4*)A;
    #pragma unroll
    for (int kc = 0; kc < K / KC; kc++) {
        __syncthreads();
        #pragma unroll
        for (int j = 0; j < 2; j++)
            ((float4*)sWc)[t + j * 256] =
                ((const float4*)(W + (size_t)kc * KC * HID))[t + j * 256];
        #pragma unroll
        for (int j = 0; j < 2; j++) {
            int i = t + j * 256;
            int r = i >> 3, kv = i & 7;
            int node = node0 + r;
            float4 v = make_float4(0.f, 0.f, 0.f, 0.f);
            if (node < n) v = Av[(size_t)node * (K / 4) + kc * (KC / 4) + kv];
            float4* dst = (float4*)(sx2 + (size_t)r * KC + kv * 4);
            dst[0] = make_float4(v.x, v.x, v.y, v.y);
            dst[1] = make_float4(v.z, v.z, v.w, v.w);
        }
        __syncthreads();
        #pragma unroll
        for (int k = 0; k < KC; k++) {
            ulonglong2 wv = ((const ulonglong2*)sWc)[(size_t)k * 16 + tx];
            #pragma unroll
            for (int i = 0; i < 4; i++) {
                unsigned long long aa = sx2[(size_t)(ty * 4 + i) * KC + k];
                asm("fma.rn.f32x2 %0, %1, %2, %0;" : "+l"(acc[i][0]) : "l"(aa), "l"(wv.x));
                asm("fma.rn.f32x2 %0, %1, %2, %0;" : "+l"(acc[i][1]) : "l"(aa), "l"(wv.y));
            }
        }
    }

    #pragma unroll
    for (int i = 0; i < 4; i++) {
        int node = node0 + ty * 4 + i;
        if (node >= n) break;
        unsigned lo0, hi0, lo1, hi1;
        asm("mov.b64 {%0, %1}, %2;" : "=r"(lo0), "=r"(hi0) : "l"(acc[i][0]));
        asm("mov.b64 {%0, %1}, %2;" : "=r"(lo1), "=r"(hi1) : "l"(acc[i][1]));
        ((float4*)Oraw)[(size_t)node * (HID / 4) + tx] =
            make_float4(__uint_as_float(lo0), __uint_as_float(hi0),
                        __uint_as_float(lo1), __uint_as_float(hi1));
    }
}

// ---- plain register-blocked GEMM (layer 2) ----
template<int K>
__global__ void __launch_bounds__(256, 4) k_gemm(
        const float* __restrict__ Aext, int in_sel, int raw_sel,
        const float* __restrict__ W, int n) {
    constexpr int KC = 32;
    __shared__ float sWc[KC * HID];
    __shared__ unsigned long long sx2[64 * KC];
    const float* A = (in_sel < 0) ? Aext : bufptr(in_sel);
    float* Oraw = bufptr(raw_sel);
    int t  = threadIdx.x;
    int tx = t & 15, ty = t >> 4;
    int node0 = blockIdx.x * 64;

    unsigned long long acc[4][2];
    #pragma unroll
    for (int i = 0; i < 4; i++) { acc[i][0] = 0ull; acc[i][1] = 0ull; }

    const float4* Av = (const float4*)A;
    #pragma unroll
    for (int kc = 0; kc < K / KC; kc++) {
        __syncthreads();
        #pragma unroll
        for (int j = 0; j < 2; j++)
            ((float4*)sWc)[t + j * 256] =
                ((const float4*)(W + (size_t)kc * KC * HID))[t + j * 256];
        #pragma unroll
        for (int j = 0; j < 2; j++) {
            int i = t + j * 256;
            int r = i >> 3, kv = i & 7;
            int node = node0 + r;
            float4 v = make_float4(0.f, 0.f, 0.f, 0.f);
            if (node < n) v = Av[(size_t)node * (K / 4) + kc * (KC / 4) + kv];
            float4* dst = (float4*)(sx2 + (size_t)r * KC + kv * 4);
            dst[0] = make_float4(v.x, v.x, v.y, v.y);
            dst[1] = make_float4(v.z, v.z, v.w, v.w);
        }
        __syncthreads();
        #pragma unroll
        for (int k = 0; k < KC; k++) {
            ulonglong2 wv = ((const ulonglong2*)sWc)[(size_t)k * 16 + tx];
            #pragma unroll
            for (int i = 0; i < 4; i++) {
                unsigned long long aa = sx2[(size_t)(ty * 4 + i) * KC + k];
                asm("fma.rn.f32x2 %0, %1, %2, %0;" : "+l"(acc[i][0]) : "l"(aa), "l"(wv.x));
                asm("fma.rn.f32x2 %0, %1, %2, %0;" : "+l"(acc[i][1]) : "l"(aa), "l"(wv.y));
            }
        }
    }

    #pragma unroll
    for (int i = 0; i < 4; i++) {
        int node = node0 + ty * 4 + i;
        if (node >= n) break;
        unsigned lo0, hi0, lo1, hi1;
        asm("mov.b64 {%0, %1}, %2;" : "=r"(lo0), "=r"(hi0) : "l"(acc[i][0]));
        asm("mov.b64 {%0, %1}, %2;" : "=r"(lo1), "=r"(hi1) : "l"(acc[i][1]));
        ((float4*)Oraw)[(size_t)node * (HID / 4) + tx] =
            make_float4(__uint_as_float(lo0), __uint_as_float(hi0),
                        __uint_as_float(lo1), __uint_as_float(hi1));
    }
}

// ---- shared CSR accumulate (4-wide MLP): dinv^2*raw_row + sum(norm*raw[src]) ----
__device__ __forceinline__ float4 csr_accum(const float* __restrict__ raw,
                                            int node, int i) {
    int end = g_off[node], cnt = g_cnt[node], e = end - cnt;
    float dv = g_dinv[node];
    float s2 = dv * dv;
    float4 acc = ((const float4*)(raw + (size_t)node * HID))[i];
    acc.x *= s2; acc.y *= s2; acc.z *= s2; acc.w *= s2;
    for (; e + 3 < end; e += 4) {
        int2 p0 = g_epack[e],     p1 = g_epack[e + 1];
        int2 p2 = g_epack[e + 2], p3 = g_epack[e + 3];
        float4 v0 = __ldg((const float4*)(raw + (size_t)p0.x * HID) + i);
        float4 v1 = __ldg((const float4*)(raw + (size_t)p1.x * HID) + i);
        float4 v2 = __ldg((const float4*)(raw + (size_t)p2.x * HID) + i);
        float4 v3 = __ldg((const float4*)(raw + (size_t)p3.x * HID) + i);
        float n0 = __int_as_float(p0.y), n1 = __int_as_float(p1.y);
        float n2 = __int_as_float(p2.y), n3 = __int_as_float(p3.y);
        acc.x += v0.x * n0; acc.y += v0.y * n0; acc.z += v0.z * n0; acc.w += v0.w * n0;
        acc.x += v1.x * n1; acc.y += v1.y * n1; acc.z += v1.z * n1; acc.w += v1.w * n1;
        acc.x += v2.x * n2; acc.y += v2.y * n2; acc.z += v2.z * n2; acc.w += v2.w * n2;
        acc.x += v3.x * n3; acc.y += v3.y * n3; acc.z += v3.z * n3; acc.w += v3.w * n3;
    }
    for (; e < end; e++) {
        int2 p0 = g_epack[e];
        float n0 = __int_as_float(p0.y);
        float4 v0 = __ldg((const float4*)(raw + (size_t)p0.x * HID) + i);
        acc.x += v0.x * n0; acc.y += v0.y * n0; acc.z += v0.z * n0; acc.w += v0.w * n0;
    }
    return acc;
}

// ---- layer-1 aggregation: half-warp per node; fused bias + relu ----
__global__ void k_agg(int in_sel, int out_sel, const float* __restrict__ b, int n) {
    int t = threadIdx.x;
    int node = blockIdx.x * 16 + (t >> 4);
    if (node >= n) return;
    int i = t & 15;
    const float* raw = bufptr(in_sel);
    float* outb = bufptr(out_sel);
    float4 acc = csr_accum(raw, node, i);
    float4 bb = ((const float4*)b)[i];
    acc.x = fmaxf(acc.x + bb.x, 0.f); acc.y = fmaxf(acc.y + bb.y, 0.f);
    acc.z = fmaxf(acc.z + bb.z, 0.f); acc.w = fmaxf(acc.w + bb.w, 0.f);
    ((float4*)(outb + (size_t)node * HID))[i] = acc;
}

// ---- layer-2 aggregation fused with output head ----
__global__ void k_agg_out(int in_sel, const float* __restrict__ b2,
                          const float* __restrict__ Wout,
                          const float* __restrict__ bout,
                          float* __restrict__ out, int n) {
    constexpr int RP = HID + 4;                 // padded row stride (bank-safe)
    __shared__ float sW[HID * NCLS];            // 4 KB
    __shared__ float sh[16 * RP];
    int t = threadIdx.x;                        // 256 threads
    ((float4*)sW)[t] = ((const float4*)Wout)[t];    // HID*NCLS/4 == 256
    int node = blockIdx.x * 16 + (t >> 4);
    int i = t & 15;
    float4 acc = make_float4(0.f, 0.f, 0.f, 0.f);
    if (node < n) {
        const float* raw = bufptr(in_sel);
        acc = csr_accum(raw, node, i);
        float4 bb = ((const float4*)b2)[i];
        acc.x = fmaxf(acc.x + bb.x, 0.f); acc.y = fmaxf(acc.y + bb.y, 0.f);
        acc.z = fmaxf(acc.z + bb.z, 0.f); acc.w = fmaxf(acc.w + bb.w, 0.f);
    }
    ((float4*)(sh + (t >> 4) * RP))[i] = acc;
    __syncthreads();
    if (node >= n) return;
    int c = i;
    const float* hr = sh + (t >> 4) * RP;
    float lg = bout[c];
    #pragma unroll
    for (int k = 0; k < HID; k++)
        lg += hr[k] * sW[k * NCLS + c];
    float m = lg;
    #pragma unroll
    for (int o = 8; o; o >>= 1) m = fmaxf(m, __shfl_xor_sync(0xffffffffu, m, o, 16));
    float e = __expf(lg - m);
    float s = e;
    #pragma unroll
    for (int o = 8; o; o >>= 1) s += __shfl_xor_sync(0xffffffffu, s, o, 16);
    out[(size_t)node * NCLS + c] = e / s;
}

extern "C" void kernel_launch(void* const* d_in, const int* in_sizes, int n_in,
                              void* d_out, int out_size) {
    const float* x    = (const float*)d_in[0];
    const void*  ei   = d_in[1];
    const float* W1   = (const float*)d_in[2];
    const float* b1   = (const float*)d_in[3];
    const float* W2   = (const float*)d_in[4];
    const float* b2   = (const float*)d_in[5];
    const float* Wout = (const float*)d_in[6];
    const float* bout = (const float*)d_in[7];
    float* out = (float*)d_out;

    int       n = in_sizes[0] / FEAT;
    long long E = (long long)in_sizes[1] / 2;

    int nb_n  = (n + 255) / 256;
    int nb_e  = (int)((E + 255) / 256);       // 1 edge per thread
    int nb_gm = (n + 63) / 64;
    int nb_ag = (n + 15) / 16;

    // CSR build (place overlapped with gemm1 below)
    k_prep<<<nb_n, 256>>>(ei, n);
    k_deg<<<nb_e, 256>>>(ei, E);
    k_scan<<<1, 1024>>>(n);

    // fused + interleaved: gemm1 (x@W1 -> bufA) + CSR placement
    int total = nb_gm + nb_e;
    int R = total / nb_gm; if (R < 1) R = 1;
    k_gemm_place<FEAT><<<total, 256>>>(x, -1, 0, W1, n, ei, E, nb_gm, R);

    // layer 1 aggregation: agg(+b1,relu) -> bufB
    k_agg<<<nb_ag, 256>>>(0, 1, b1, n);

    // layer 2: raw = bufB@W2 -> bufA
    k_gemm<HID><<<nb_gm, 256>>>(nullptr, 1, 0, W2, n);

    // agg2(+b2,relu) + head -> out
    k_agg_out<<<nb_ag, 256>>>(0, b2, Wout, bout, out, n);
}

// round 15
// speedup vs baseline: 1.1190x; 1.0612x over previous
#include <cuda_runtime.h>
#include <cuda_bf16.h>

#define NMAX   50000
#define EMAX   800000
#define FEAT   128
#define HID    64
#define NCLS   16

// ---- device scratch (no allocations allowed) ----
// g_cnt is SELF-RESTORING: zero at module load, re-zeroed by k_agg_out at the
// end of every call, so no prep kernel is needed.
__device__ int   g_cnt [NMAX];     // in-degree (excl. self-loop)
__device__ int   g_off [NMAX];     // CSR offsets (destructively consumed by place)
__device__ float g_dinv[NMAX];
__device__ int2  g_epack[EMAX];    // CSR: (src, norm_bits) sorted by dst
__device__ float g_bufA[(size_t)NMAX * HID];
__device__ float g_bufB[(size_t)NMAX * HID];
__device__ int   g_is64;

__device__ __forceinline__ float* bufptr(int sel) { return sel ? g_bufB : g_bufA; }

__device__ __forceinline__ int edge_at(const void* __restrict__ idx, long long i) {
    if (g_is64) return (int)((const long long*)idx)[i];
    return ((const int*)idx)[i];
}

// ---- count in-degrees; per-block dtype self-detection (no global dependency).
//      int32 data read as int64 packs (lo,hi): passes range check only if every
//      sampled hi-word is 0 (p ~ 2e-5 each, 32 samples -> impossible). ----
__global__ void k_deg(const void* __restrict__ idx, long long E, int n) {
    __shared__ int s64;
    if (threadIdx.x < 32) {
        long long v = ((const long long*)idx)[threadIdx.x];
        unsigned m = __ballot_sync(0xffffffffu, v >= 0 && v < n);
        if (threadIdx.x == 0) {
            int is64 = (m == 0xffffffffu);
            s64 = is64;
            if (blockIdx.x == 0) g_is64 = is64;   // publish for place half
        }
    }
    __syncthreads();
    int is64 = s64;
    long long e = (long long)blockIdx.x * 256 + threadIdx.x;
    if (e >= E) return;
    int d = is64 ? (int)((const long long*)idx)[E + e]
                 : ((const int*)idx)[E + e];
    atomicAdd(&g_cnt[d], 1);
}

// ---- single-block exclusive scan of g_cnt -> g_off (4/thread) ; also dinv ----
__global__ void k_scan(int n) {
    __shared__ int wsum[32];
    __shared__ int s_carry;
    int t = threadIdx.x;                 // 1024 threads
    int lane = t & 31, wid = t >> 5;
    if (t == 0) s_carry = 0;
    __syncthreads();
    int nIter = (n + 4095) / 4096;
    for (int it = 0; it < nIter; it++) {
        int base = it * 4096 + t * 4;
        int4 c = make_int4(0, 0, 0, 0);
        if (base + 3 < n) c = *(const int4*)(g_cnt + base);
        else {
            if (base     < n) c.x = g_cnt[base];
            if (base + 1 < n) c.y = g_cnt[base + 1];
            if (base + 2 < n) c.z = g_cnt[base + 2];
        }
        int v = c.x + c.y + c.z + c.w;
        int x = v;
        #pragma unroll
        for (int o = 1; o < 32; o <<= 1) {
            int y = __shfl_up_sync(0xffffffffu, x, o);
            if (lane >= o) x += y;
        }
        if (lane == 31) wsum[wid] = x;
        __syncthreads();
        if (t < 32) {
            int w = wsum[t], xs = w;
            #pragma unroll
            for (int o = 1; o < 32; o <<= 1) {
                int y = __shfl_up_sync(0xffffffffu, xs, o);
                if (t >= o) xs += y;
            }
            wsum[t] = xs - w;            // exclusive warp prefix
        }
        __syncthreads();
        int excl = x - v + wsum[wid] + s_carry;
        if (base + 3 < n) {
            *(int4*)(g_off + base) = make_int4(excl, excl + c.x,
                                               excl + c.x + c.y,
                                               excl + c.x + c.y + c.z);
            *(float4*)(g_dinv + base) = make_float4(
                rsqrtf((float)c.x + 1.0f), rsqrtf((float)c.y + 1.0f),
                rsqrtf((float)c.z + 1.0f), rsqrtf((float)c.w + 1.0f));
        } else {
            int run = excl;
            if (base < n)     { g_off[base]   = run; g_dinv[base]   = rsqrtf((float)c.x + 1.0f); run += c.x; }
            if (base + 1 < n) { g_off[base+1] = run; g_dinv[base+1] = rsqrtf((float)c.y + 1.0f); run += c.y; }
            if (base + 2 < n) { g_off[base+2] = run; g_dinv[base+2] = rsqrtf((float)c.z + 1.0f); }
        }
        __syncthreads();
        if (t == 1023) s_carry = excl + v;
        __syncthreads();
    }
}

// ---- FUSED: gemm1 (blocks [0,nGemm)) + CSR placement (remaining blocks). ----
template<int K>
__global__ void __launch_bounds__(256, 4) k_gemm_place(
        const float* __restrict__ Aext, int in_sel, int raw_sel,
        const float* __restrict__ W, int n,
        const void* __restrict__ idx, long long E, int nGemm) {
    constexpr int KC = 32;
    __shared__ float sWc[KC * HID];               // 8KB chunk of W
    __shared__ unsigned long long sx2[64 * KC];   // 16KB (a,a) duplicated
    int t = threadIdx.x;

    if (blockIdx.x >= nGemm) {
        // ---- placement half: 1 edge per thread ----
        long long e = (long long)(blockIdx.x - nGemm) * 256 + t;
        if (e < E) {
            int s = edge_at(idx, e);
            int d = edge_at(idx, E + e);
            int pos = atomicAdd(&g_off[d], 1);
            float norm = g_dinv[s] * g_dinv[d];
            g_epack[pos] = make_int2(s, __float_as_int(norm));
        }
        return;
    }

    // ---- gemm half ----
    const float* A = (in_sel < 0) ? Aext : bufptr(in_sel);
    float* Oraw = bufptr(raw_sel);
    int tx = t & 15, ty = t >> 4;
    int node0 = blockIdx.x * 64;

    unsigned long long acc[4][2];
    #pragma unroll
    for (int i = 0; i < 4; i++) { acc[i][0] = 0ull; acc[i][1] = 0ull; }

    const float4* Av = (const float4*)A;
    #pragma unroll
    for (int kc = 0; kc < K / KC; kc++) {
        __syncthreads();
        #pragma unroll
        for (int j = 0; j < 2; j++)
            ((float4*)sWc)[t + j * 256] =
                ((const float4*)(W + (size_t)kc * KC * HID))[t + j * 256];
        #pragma unroll
        for (int j = 0; j < 2; j++) {
            int i = t + j * 256;
            int r = i >> 3, kv = i & 7;
            int node = node0 + r;
            float4 v = make_float4(0.f, 0.f, 0.f, 0.f);
            if (node < n) v = Av[(size_t)node * (K / 4) + kc * (KC / 4) + kv];
            float4* dst = (float4*)(sx2 + (size_t)r * KC + kv * 4);
            dst[0] = make_float4(v.x, v.x, v.y, v.y);
            dst[1] = make_float4(v.z, v.z, v.w, v.w);
        }
        __syncthreads();
        #pragma unroll
        for (int k = 0; k < KC; k++) {
            ulonglong2 wv = ((const ulonglong2*)sWc)[(size_t)k * 16 + tx];
            #pragma unroll
            for (int i = 0; i < 4; i++) {
                unsigned long long aa = sx2[(size_t)(ty * 4 + i) * KC + k];
                asm("fma.rn.f32x2 %0, %1, %2, %0;" : "+l"(acc[i][0]) : "l"(aa), "l"(wv.x));
                asm("fma.rn.f32x2 %0, %1, %2, %0;" : "+l"(acc[i][1]) : "l"(aa), "l"(wv.y));
            }
        }
    }

    #pragma unroll
    for (int i = 0; i < 4; i++) {
        int node = node0 + ty * 4 + i;
        if (node >= n) break;
        unsigned lo0, hi0, lo1, hi1;
        asm("mov.b64 {%0, %1}, %2;" : "=r"(lo0), "=r"(hi0) : "l"(acc[i][0]));
        asm("mov.b64 {%0, %1}, %2;" : "=r"(lo1), "=r"(hi1) : "l"(acc[i][1]));
        ((float4*)Oraw)[(size_t)node * (HID / 4) + tx] =
            make_float4(__uint_as_float(lo0), __uint_as_float(hi0),
                        __uint_as_float(lo1), __uint_as_float(hi1));
    }
}

// ---- plain register-blocked GEMM (layer 2) ----
template<int K>
__global__ void __launch_bounds__(256, 4) k_gemm(
        const float* __restrict__ Aext, int in_sel, int raw_sel,
        const float* __restrict__ W, int n) {
    constexpr int KC = 32;
    __shared__ float sWc[KC * HID];
    __shared__ unsigned long long sx2[64 * KC];
    const float* A = (in_sel < 0) ? Aext : bufptr(in_sel);
    float* Oraw = bufptr(raw_sel);
    int t  = threadIdx.x;
    int tx = t & 15, ty = t >> 4;
    int node0 = blockIdx.x * 64;

    unsigned long long acc[4][2];
    #pragma unroll
    for (int i = 0; i < 4; i++) { acc[i][0] = 0ull; acc[i][1] = 0ull; }

    const float4* Av = (const float4*)A;
    #pragma unroll
    for (int kc = 0; kc < K / KC; kc++) {
        __syncthreads();
        #pragma unroll
        for (int j = 0; j < 2; j++)
            ((float4*)sWc)[t + j * 256] =
                ((const float4*)(W + (size_t)kc * KC * HID))[t + j * 256];
        #pragma unroll
        for (int j = 0; j < 2; j++) {
            int i = t + j * 256;
            int r = i >> 3, kv = i & 7;
            int node = node0 + r;
            float4 v = make_float4(0.f, 0.f, 0.f, 0.f);
            if (node < n) v = Av[(size_t)node * (K / 4) + kc * (KC / 4) + kv];
            float4* dst = (float4*)(sx2 + (size_t)r * KC + kv * 4);
            dst[0] = make_float4(v.x, v.x, v.y, v.y);
            dst[1] = make_float4(v.z, v.z, v.w, v.w);
        }
        __syncthreads();
        #pragma unroll
        for (int k = 0; k < KC; k++) {
            ulonglong2 wv = ((const ulonglong2*)sWc)[(size_t)k * 16 + tx];
            #pragma unroll
            for (int i = 0; i < 4; i++) {
                unsigned long long aa = sx2[(size_t)(ty * 4 + i) * KC + k];
                asm("fma.rn.f32x2 %0, %1, %2, %0;" : "+l"(acc[i][0]) : "l"(aa), "l"(wv.x));
                asm("fma.rn.f32x2 %0, %1, %2, %0;" : "+l"(acc[i][1]) : "l"(aa), "l"(wv.y));
            }
        }
    }

    #pragma unroll
    for (int i = 0; i < 4; i++) {
        int node = node0 + ty * 4 + i;
        if (node >= n) break;
        unsigned lo0, hi0, lo1, hi1;
        asm("mov.b64 {%0, %1}, %2;" : "=r"(lo0), "=r"(hi0) : "l"(acc[i][0]));
        asm("mov.b64 {%0, %1}, %2;" : "=r"(lo1), "=r"(hi1) : "l"(acc[i][1]));
        ((float4*)Oraw)[(size_t)node * (HID / 4) + tx] =
            make_float4(__uint_as_float(lo0), __uint_as_float(hi0),
                        __uint_as_float(lo1), __uint_as_float(hi1));
    }
}

// ---- shared CSR accumulate (4-wide MLP): dinv^2*raw_row + sum(norm*raw[src]) ----
__device__ __forceinline__ float4 csr_accum(const float* __restrict__ raw,
                                            int node, int i) {
    int end = g_off[node], cnt = g_cnt[node], e = end - cnt;
    float dv = g_dinv[node];
    float s2 = dv * dv;
    float4 acc = ((const float4*)(raw + (size_t)node * HID))[i];
    acc.x *= s2; acc.y *= s2; acc.z *= s2; acc.w *= s2;
    for (; e + 3 < end; e += 4) {
        int2 p0 = g_epack[e],     p1 = g_epack[e + 1];
        int2 p2 = g_epack[e + 2], p3 = g_epack[e + 3];
        float4 v0 = __ldg((const float4*)(raw + (size_t)p0.x * HID) + i);
        float4 v1 = __ldg((const float4*)(raw + (size_t)p1.x * HID) + i);
        float4 v2 = __ldg((const float4*)(raw + (size_t)p2.x * HID) + i);
        float4 v3 = __ldg((const float4*)(raw + (size_t)p3.x * HID) + i);
        float n0 = __int_as_float(p0.y), n1 = __int_as_float(p1.y);
        float n2 = __int_as_float(p2.y), n3 = __int_as_float(p3.y);
        acc.x += v0.x * n0; acc.y += v0.y * n0; acc.z += v0.z * n0; acc.w += v0.w * n0;
        acc.x += v1.x * n1; acc.y += v1.y * n1; acc.z += v1.z * n1; acc.w += v1.w * n1;
        acc.x += v2.x * n2; acc.y += v2.y * n2; acc.z += v2.z * n2; acc.w += v2.w * n2;
        acc.x += v3.x * n3; acc.y += v3.y * n3; acc.z += v3.z * n3; acc.w += v3.w * n3;
    }
    for (; e < end; e++) {
        int2 p0 = g_epack[e];
        float n0 = __int_as_float(p0.y);
        float4 v0 = __ldg((const float4*)(raw + (size_t)p0.x * HID) + i);
        acc.x += v0.x * n0; acc.y += v0.y * n0; acc.z += v0.z * n0; acc.w += v0.w * n0;
    }
    return acc;
}

// ---- layer-1 aggregation: half-warp per node; fused bias + relu ----
__global__ void k_agg(int in_sel, int out_sel, const float* __restrict__ b, int n) {
    int t = threadIdx.x;
    int node = blockIdx.x * 16 + (t >> 4);
    if (node >= n) return;
    int i = t & 15;
    const float* raw = bufptr(in_sel);
    float* outb = bufptr(out_sel);
    float4 acc = csr_accum(raw, node, i);
    float4 bb = ((const float4*)b)[i];
    acc.x = fmaxf(acc.x + bb.x, 0.f); acc.y = fmaxf(acc.y + bb.y, 0.f);
    acc.z = fmaxf(acc.z + bb.z, 0.f); acc.w = fmaxf(acc.w + bb.w, 0.f);
    ((float4*)(outb + (size_t)node * HID))[i] = acc;
}

// ---- layer-2 aggregation fused with output head; re-zeroes g_cnt at end ----
__global__ void k_agg_out(int in_sel, const float* __restrict__ b2,
                          const float* __restrict__ Wout,
                          const float* __restrict__ bout,
                          float* __restrict__ out, int n) {
    constexpr int RP = HID + 4;                 // padded row stride (bank-safe)
    __shared__ float sW[HID * NCLS];            // 4 KB
    __shared__ float sh[16 * RP];
    int t = threadIdx.x;                        // 256 threads
    ((float4*)sW)[t] = ((const float4*)Wout)[t];    // HID*NCLS/4 == 256
    int node = blockIdx.x * 16 + (t >> 4);
    int i = t & 15;
    float4 acc = make_float4(0.f, 0.f, 0.f, 0.f);
    if (node < n) {
        const float* raw = bufptr(in_sel);
        acc = csr_accum(raw, node, i);
        float4 bb = ((const float4*)b2)[i];
        acc.x = fmaxf(acc.x + bb.x, 0.f); acc.y = fmaxf(acc.y + bb.y, 0.f);
        acc.z = fmaxf(acc.z + bb.z, 0.f); acc.w = fmaxf(acc.w + bb.w, 0.f);
    }
    ((float4*)(sh + (t >> 4) * RP))[i] = acc;
    __syncthreads();
    // self-restore: all csr_accum reads of g_cnt are complete past the barrier
    if (i == 0 && node < n) g_cnt[node] = 0;
    if (node >= n) return;
    int c = i;
    const float* hr = sh + (t >> 4) * RP;
    float lg = bout[c];
    #pragma unroll
    for (int k = 0; k < HID; k++)
        lg += hr[k] * sW[k * NCLS + c];
    float m = lg;
    #pragma unroll
    for (int o = 8; o; o >>= 1) m = fmaxf(m, __shfl_xor_sync(0xffffffffu, m, o, 16));
    float e = __expf(lg - m);
    float s = e;
    #pragma unroll
    for (int o = 8; o; o >>= 1) s += __shfl_xor_sync(0xffffffffu, s, o, 16);
    out[(size_t)node * NCLS + c] = e / s;
}

extern "C" void kernel_launch(void* const* d_in, const int* in_sizes, int n_in,
                              void* d_out, int out_size) {
    const float* x    = (const float*)d_in[0];
    const void*  ei   = d_in[1];
    const float* W1   = (const float*)d_in[2];
    const float* b1   = (const float*)d_in[3];
    const float* W2   = (const float*)d_in[4];
    const float* b2   = (const float*)d_in[5];
    const float* Wout = (const float*)d_in[6];
    const float* bout = (const float*)d_in[7];
    float* out = (float*)d_out;

    int       n = in_sizes[0] / FEAT;
    long long E = (long long)in_sizes[1] / 2;

    int nb_e  = (int)((E + 255) / 256);       // 1 edge per thread
    int nb_gm = (n + 63) / 64;
    int nb_ag = (n + 15) / 16;

    // CSR build (g_cnt self-restored by previous call / module load)
    k_deg<<<nb_e, 256>>>(ei, E, n);
    k_scan<<<1, 1024>>>(n);

    // fused: gemm1 (x@W1 -> bufA) + CSR placement, one launch
    k_gemm_place<FEAT><<<nb_gm + nb_e, 256>>>(x, -1, 0, W1, n, ei, E, nb_gm);

    // layer 1 aggregation: agg(+b1,relu) -> bufB
    k_agg<<<nb_ag, 256>>>(0, 1, b1, n);

    // layer 2: raw = bufB@W2 -> bufA
    k_gemm<HID><<<nb_gm, 256>>>(nullptr, 1, 0, W2, n);

    // agg2(+b2,relu) + head -> out ; re-zeroes g_cnt for next call
    k_agg_out<<<nb_ag, 256>>>(0, b2, Wout, bout, out, n);
}